// round 3
// baseline (speedup 1.0000x reference)
#include <cuda_runtime.h>
#include <math.h>

// Problem constants
#define NB    8192          // batch N
#define TT    48            // timesteps
#define HH    256           // hidden
#define NENV  10
#define NIN   16
#define FOURH 1024          // 4*H

// GEMM tile config
#define BM 128              // rows per block (batch)
#define BSC 128             // stored gate-cols per block (= 32 h * 4 gates)
#define KB 16               // k-tile

// ---------------------------------------------------------------------------
// Scratch (static device globals; allocation inside kernel_launch is banned)
// ---------------------------------------------------------------------------
__device__ float g_h[2][2][NB * HH];          // [layer][pingpong][N*H]
__device__ float g_c[2][NB * HH];             // [layer][N*H]
__device__ float g_Whh_t[2][HH * FOURH];      // [layer][k*1024 + s], s = h*4+gate
__device__ float g_Wih1_t[HH * FOURH];        // layer-1 input weights, same layout
__device__ float g_Wc_t[NIN * FOURH];         // folded W_ih0 @ W_in, [f*1024 + s]
__device__ float g_bias[2][FOURH];            // combined b_ih+b_hh, s-layout

__device__ __forceinline__ float sigm(float v) {
    return 1.0f / (1.0f + __expf(-v));
}

// ---------------------------------------------------------------------------
// Prep kernels (run every call; cheap)
// ---------------------------------------------------------------------------
__global__ void zero_kernel() {
    const size_t tot = (size_t)NB * HH;
    for (size_t i = (size_t)blockIdx.x * blockDim.x + threadIdx.x; i < tot;
         i += (size_t)gridDim.x * blockDim.x) {
        g_h[0][0][i] = 0.0f;
        g_h[1][0][i] = 0.0f;
        g_c[0][i] = 0.0f;
        g_c[1][i] = 0.0f;
    }
}

// Transpose+permute W_hh (both layers), W_ih (layer 1), combine biases.
// Target layout: Wt[k*1024 + s], s = h*4 + gate; gate order i,f,g,o.
__global__ void prep_transpose(const float* __restrict__ W_ih,
                               const float* __restrict__ W_hh,
                               const float* __restrict__ b_ih,
                               const float* __restrict__ b_hh) {
    const int tot = 262144 * 3 + 2048;
    for (int i = blockIdx.x * blockDim.x + threadIdx.x; i < tot;
         i += gridDim.x * blockDim.x) {
        if (i < 524288) {
            int l = i >> 18;
            int r = i & 262143;
            int k = r >> 10;
            int s = r & 1023;
            int g = s & 3;
            int h = s >> 2;
            g_Whh_t[l][r] = W_hh[l * 262144 + (g * HH + h) * HH + k];
        } else if (i < 786432) {
            int r = i - 524288;
            int k = r >> 10;
            int s = r & 1023;
            int g = s & 3;
            int h = s >> 2;
            g_Wih1_t[r] = W_ih[262144 + (g * HH + h) * HH + k];
        } else {
            int j = i - 786432;
            int l = j >> 10;
            int s = j & 1023;
            int g = s & 3;
            int h = s >> 2;
            int row = l * FOURH + g * HH + h;
            g_bias[l][s] = b_ih[row] + b_hh[row];
        }
    }
}

// Fold input projection into layer-0 ih weights: Wc = W_ih0 @ W_in  -> [f][s]
__global__ void prep_wc(const float* __restrict__ W_in,
                        const float* __restrict__ W_ih) {
    int i = blockIdx.x * blockDim.x + threadIdx.x;
    if (i >= NIN * FOURH) return;
    int f = i & 15;
    int s = i >> 4;          // 0..1023
    int g = s & 3;
    int h = s >> 2;
    const float* wr = W_ih + (g * HH + h) * HH;   // layer 0 row
    float acc = 0.0f;
    #pragma unroll 8
    for (int k = 0; k < HH; k++)
        acc = fmaf(wr[k], W_in[k * NIN + f], acc);
    g_Wc_t[f * FOURH + s] = acc;
}

// ---------------------------------------------------------------------------
// Fused LSTM step: gates GEMM (+ cell epilogue). 256 threads, 128x128 tile.
// Column permutation: stored col s_local = hc*4 + gate so each thread's 8
// contiguous accumulator cols = {2 h-values} x {4 gates}.
// ---------------------------------------------------------------------------
__device__ __forceinline__ void load_tile_A(float (*As)[BM],
                                            const float* __restrict__ Ag,
                                            int rowbase, int k0, int tid) {
    int r = tid >> 1;
    int q = tid & 1;
    const float* src = Ag + (size_t)(rowbase + r) * HH + k0 + q * 8;
    float4 v0 = *(const float4*)src;
    float4 v1 = *(const float4*)(src + 4);
    int kb = q * 8;
    As[kb + 0][r] = v0.x; As[kb + 1][r] = v0.y;
    As[kb + 2][r] = v0.z; As[kb + 3][r] = v0.w;
    As[kb + 4][r] = v1.x; As[kb + 5][r] = v1.y;
    As[kb + 6][r] = v1.z; As[kb + 7][r] = v1.w;
}

__device__ __forceinline__ void load_tile_B(float (*Bs)[BSC],
                                            const float* __restrict__ Bg,
                                            int sbase, int k0, int tid) {
    int kk = tid >> 4;
    int lane = tid & 15;
    const float* src = Bg + (size_t)(k0 + kk) * FOURH + sbase + lane * 8;
    *(float4*)&Bs[kk][lane * 8]     = *(const float4*)src;
    *(float4*)&Bs[kk][lane * 8 + 4] = *(const float4*)(src + 4);
}

__device__ __forceinline__ void compute_tile(const float (*As)[BM],
                                             const float (*Bs)[BSC],
                                             float acc[8][8], int tx, int ty) {
    #pragma unroll
    for (int k = 0; k < KB; k++) {
        float a[8], b[8];
        *(float4*)&a[0] = *(const float4*)&As[k][ty * 8];
        *(float4*)&a[4] = *(const float4*)&As[k][ty * 8 + 4];
        *(float4*)&b[0] = *(const float4*)&Bs[k][tx * 8];
        *(float4*)&b[4] = *(const float4*)&Bs[k][tx * 8 + 4];
        #pragma unroll
        for (int i = 0; i < 8; i++)
            #pragma unroll
            for (int j = 0; j < 8; j++)
                acc[i][j] = fmaf(a[i], b[j], acc[i][j]);
    }
}

template <int LAYER>
__global__ __launch_bounds__(256, 2) void lstm_step(
    const float* __restrict__ x, const float* __restrict__ coords,
    const float* __restrict__ env, const float* __restrict__ areas,
    const float* __restrict__ bird_uv, int t) {
    __shared__ float As[KB][BM];
    __shared__ float Bs[KB][BSC];

    const int tid = threadIdx.x;
    const int tx = tid & 15;
    const int ty = tid >> 4;
    const int rowbase = blockIdx.x * BM;          // batch offset
    const int hbase = blockIdx.y * 32;            // hidden offset
    const int sbase = blockIdx.y * BSC;           // permuted-col offset

    float acc[8][8];
    #pragma unroll
    for (int i = 0; i < 8; i++)
        #pragma unroll
        for (int j = 0; j < 8; j++) acc[i][j] = 0.0f;

    if (LAYER == 0) {
        // ---- input phase: 16-feature projection via folded Wc ----
        {
            int r = tid >> 1;
            int half = tid & 1;
            int n = rowbase + r;
            if (half == 0) {
                As[0][r] = x[(size_t)n * TT + t];
                As[1][r] = coords[n * 2];
                As[2][r] = coords[n * 2 + 1];
                #pragma unroll
                for (int j = 0; j < 5; j++)
                    As[3 + j][r] = env[((size_t)n * NENV + j) * TT + t];
            } else {
                #pragma unroll
                for (int j = 5; j < 10; j++)
                    As[3 + j][r] = env[((size_t)n * NENV + j) * TT + t];
                As[13][r] = areas[n];
                As[14][r] = bird_uv[((size_t)n * 2) * TT + t];
                As[15][r] = bird_uv[((size_t)n * 2 + 1) * TT + t];
            }
            load_tile_B(Bs, g_Wc_t, sbase, 0, tid);
        }
        __syncthreads();
        compute_tile(As, Bs, acc, tx, ty);
    } else {
        // ---- input phase: h0(t) @ W_ih1^T, K=256 ----
        const float* xin = g_h[0][(t + 1) & 1];
        #pragma unroll 1
        for (int k0 = 0; k0 < HH; k0 += KB) {
            __syncthreads();
            load_tile_A(As, xin, rowbase, k0, tid);
            load_tile_B(Bs, g_Wih1_t, sbase, k0, tid);
            __syncthreads();
            compute_tile(As, Bs, acc, tx, ty);
        }
    }

    // ---- recurrent phase: h_prev @ W_hh^T, K=256 ----
    {
        const float* hprev = g_h[LAYER][t & 1];
        const float* Whh = g_Whh_t[LAYER];
        #pragma unroll 1
        for (int k0 = 0; k0 < HH; k0 += KB) {
            __syncthreads();
            load_tile_A(As, hprev, rowbase, k0, tid);
            load_tile_B(Bs, Whh, sbase, k0, tid);
            __syncthreads();
            compute_tile(As, Bs, acc, tx, ty);
        }
    }

    // ---- LSTM cell epilogue ----
    float* cst = g_c[LAYER];
    float* hout = g_h[LAYER][(t + 1) & 1];
    float bsv[8];
    #pragma unroll
    for (int j = 0; j < 8; j++)
        bsv[j] = g_bias[LAYER][sbase + tx * 8 + j];

    #pragma unroll
    for (int i = 0; i < 8; i++) {
        int n = rowbase + ty * 8 + i;
        #pragma unroll
        for (int hh = 0; hh < 2; hh++) {
            int j0 = hh * 4;
            float iv = sigm(acc[i][j0 + 0] + bsv[j0 + 0]);
            float fv = sigm(acc[i][j0 + 1] + bsv[j0 + 1]);
            float gv = tanhf(acc[i][j0 + 2] + bsv[j0 + 2]);
            float ov = sigm(acc[i][j0 + 3] + bsv[j0 + 3]);
            int hcol = hbase + tx * 2 + hh;
            size_t idx = (size_t)n * HH + hcol;
            float cn = fv * cst[idx] + iv * gv;
            cst[idx] = cn;
            hout[idx] = ov * tanhf(cn);
        }
    }
}

// ---------------------------------------------------------------------------
// Final gather: out = [h(L=0), h(L=1), c(L=0), c(L=1)], each [N,H]
// After t = 0..47, last write went to pingpong slot (47+1)&1 = 0.
// ---------------------------------------------------------------------------
__global__ void write_out(float* __restrict__ out, size_t out_elems) {
    const size_t NHv = (size_t)NB * HH;
    for (size_t i = (size_t)blockIdx.x * blockDim.x + threadIdx.x;
         i < out_elems; i += (size_t)gridDim.x * blockDim.x) {
        size_t sec = i / NHv;
        size_t r = i % NHv;
        float v;
        if (sec == 0)      v = g_h[0][0][r];
        else if (sec == 1) v = g_h[1][0][r];
        else if (sec == 2) v = g_c[0][r];
        else               v = g_c[1][r];
        out[i] = v;
    }
}

// ---------------------------------------------------------------------------
extern "C" void kernel_launch(void* const* d_in, const int* in_sizes, int n_in,
                              void* d_out, int out_size) {
    const float* x       = (const float*)d_in[0];
    const float* coords  = (const float*)d_in[1];
    const float* env     = (const float*)d_in[2];
    const float* areas   = (const float*)d_in[3];
    const float* bird_uv = (const float*)d_in[4];
    const float* W_in    = (const float*)d_in[5];
    const float* W_ih    = (const float*)d_in[6];
    const float* W_hh    = (const float*)d_in[7];
    const float* b_ih    = (const float*)d_in[8];
    const float* b_hh    = (const float*)d_in[9];
    (void)in_sizes; (void)n_in;

    zero_kernel<<<1024, 256>>>();
    prep_transpose<<<768, 256>>>(W_ih, W_hh, b_ih, b_hh);
    prep_wc<<<64, 256>>>(W_in, W_ih);

    dim3 grid(NB / BM, HH / 32);   // (64, 8)
    for (int t = 0; t < TT; t++) {
        lstm_step<0><<<grid, 256>>>(x, coords, env, areas, bird_uv, t);
        lstm_step<1><<<grid, 256>>>(x, coords, env, areas, bird_uv, t);
    }

    write_out<<<4096, 256>>>((float*)d_out, (size_t)out_size);
}